// round 14
// baseline (speedup 1.0000x reference)
#include <cuda_runtime.h>
#include <math.h>
#include <float.h>

// ---------------------------------------------------------------------------
// Tiled Gaussian splat renderer (B=1, V=1). Two-kernel graph with PDL overlap:
//  1) prep: per-gaussian projection/conic/color -> SoA + packed 8x8-tile
//     range (complement-encoded u8x4 for SIMD test) + ordered z key.
//  2) render (PDL): one 512-thread block per 8x8 tile:
//       a) cull: prefetch tbox chunks, __vcmpgeu4 test, warp-agg append
//       b) BARRIER-FREE rank sort on (ordered_z | idx): each thread scans the
//          key list once, scatter-writes by exact rank (2 barriers total)
//       c) 8 z-segment groups (64 px each) composite, chunk=64,
//          exact in-smem segment combine.  Empty tiles: zero-fill fast path.
// ---------------------------------------------------------------------------

#define MAXN  2048
#define TW    8

__device__ float4 d_rawA[MAXN], d_rawB[MAXN], d_rawC[MAXN];
__device__ unsigned int d_tbox[MAXN];    // tx0 | (255-tx1)<<8 | ty0<<16 | (255-ty1)<<24
__device__ unsigned int d_zkey[MAXN];    // ordered-float z

// Scalar inputs may arrive as int32 or float32 bit patterns.
__device__ __forceinline__ float load_scalar_f(const void* p) {
    int v = *(const int*)p;
    if (v >= -1000000 && v <= 1000000) return (float)v;
    return __int_as_float(v);
}
__device__ __forceinline__ int load_scalar_i(const void* p) {
    return (int)load_scalar_f(p);
}

__device__ __forceinline__ unsigned int float_to_ordered(float f) {
    unsigned int u = __float_as_uint(f);
    return (u & 0x80000000u) ? ~u : (u | 0x80000000u);
}

// ---------------- per-gaussian preprocess ----------------
__global__ void prep_kernel(const float* __restrict__ xyz,
                            const float* __restrict__ feat,
                            const float* __restrict__ scal,
                            const float* __restrict__ rot,
                            const float* __restrict__ opac,
                            const float* __restrict__ c2w,
                            const float* __restrict__ intr,
                            const void* nearp, const void* farp,
                            const void* pW, int npix, int N)
{
    int n = blockIdx.x * blockDim.x + threadIdx.x;
    if (n >= N) { cudaTriggerProgrammaticLaunchCompletion(); return; }
    float nearf = load_scalar_f(nearp);
    float farf  = load_scalar_f(farp);
    int W = load_scalar_i(pW);
    int H = npix / W;
    int TX = (W + TW - 1) / TW;
    int TY = (H + TW - 1) / TW;

    float4 q4 = *(const float4*)(rot + n*4);
    float qw = q4.x, qx = q4.y, qy = q4.z, qz = q4.w;
    float inr = 1.0f / (sqrtf(qw*qw + qx*qx + qy*qy + qz*qz) + 1e-8f);
    qw *= inr; qx *= inr; qy *= inr; qz *= inr;
    float R00 = 1.0f - 2.0f*(qy*qy + qz*qz);
    float R01 = 2.0f*(qx*qy - qw*qz);
    float R02 = 2.0f*(qx*qz + qw*qy);
    float R10 = 2.0f*(qx*qy + qw*qz);
    float R11 = 1.0f - 2.0f*(qx*qx + qz*qz);
    float R12 = 2.0f*(qy*qz - qw*qx);
    float R20 = 2.0f*(qx*qz - qw*qy);
    float R21 = 2.0f*(qy*qz + qw*qx);
    float R22 = 1.0f - 2.0f*(qx*qx + qy*qy);

    float s0 = scal[n*3+0], s1 = scal[n*3+1], s2 = scal[n*3+2];
    float M00 = R00*s0, M01 = R01*s1, M02 = R02*s2;
    float M10 = R10*s0, M11 = R11*s1, M12 = R12*s2;
    float M20 = R20*s0, M21 = R21*s1, M22 = R22*s2;

    float C00 = M00*M00 + M01*M01 + M02*M02;
    float C01 = M00*M10 + M01*M11 + M02*M12;
    float C02 = M00*M20 + M01*M21 + M02*M22;
    float C11 = M10*M10 + M11*M11 + M12*M12;
    float C12 = M10*M20 + M11*M21 + M12*M22;
    float C22 = M20*M20 + M21*M21 + M22*M22;

    float A00 = c2w[0], A01 = c2w[1], A02 = c2w[2],  tx = c2w[3];
    float A10 = c2w[4], A11 = c2w[5], A12 = c2w[6],  ty = c2w[7];
    float A20 = c2w[8], A21 = c2w[9], A22 = c2w[10], tz = c2w[11];
    float i00 = A11*A22 - A12*A21, i01 = A02*A21 - A01*A22, i02 = A01*A12 - A02*A11;
    float i10 = A12*A20 - A10*A22, i11 = A00*A22 - A02*A20, i12 = A02*A10 - A00*A12;
    float i20 = A10*A21 - A11*A20, i21 = A01*A20 - A00*A21, i22 = A00*A11 - A01*A10;
    float dinv = 1.0f / (A00*i00 + A01*i10 + A02*i20);
    float Rw00 = i00*dinv, Rw01 = i01*dinv, Rw02 = i02*dinv;
    float Rw10 = i10*dinv, Rw11 = i11*dinv, Rw12 = i12*dinv;
    float Rw20 = i20*dinv, Rw21 = i21*dinv, Rw22 = i22*dinv;
    float t0 = -(Rw00*tx + Rw01*ty + Rw02*tz);
    float t1 = -(Rw10*tx + Rw11*ty + Rw12*tz);
    float t2 = -(Rw20*tx + Rw21*ty + Rw22*tz);

    float x0 = xyz[n*3+0], x1 = xyz[n*3+1], x2 = xyz[n*3+2];
    float p0 = Rw00*x0 + Rw01*x1 + Rw02*x2 + t0;
    float p1 = Rw10*x0 + Rw11*x1 + Rw12*x2 + t1;
    float p2 = Rw20*x0 + Rw21*x1 + Rw22*x2 + t2;

    float z  = p2;
    float zs = fmaxf(z, 1e-4f);
    float izs = 1.0f / zs;
    float fx = intr[0], fy = intr[1], cx = intr[2], cy = intr[3];
    float u = fx * p0 * izs + cx;
    float v = fy * p1 * izs + cy;

    float T00 = Rw00*C00 + Rw01*C01 + Rw02*C02;
    float T01 = Rw00*C01 + Rw01*C11 + Rw02*C12;
    float T02 = Rw00*C02 + Rw01*C12 + Rw02*C22;
    float T10 = Rw10*C00 + Rw11*C01 + Rw12*C02;
    float T11 = Rw10*C01 + Rw11*C11 + Rw12*C12;
    float T12 = Rw10*C02 + Rw11*C12 + Rw12*C22;
    float T20 = Rw20*C00 + Rw21*C01 + Rw22*C02;
    float T21 = Rw20*C01 + Rw21*C11 + Rw22*C12;
    float T22 = Rw20*C02 + Rw21*C12 + Rw22*C22;
    float cc00 = T00*Rw00 + T01*Rw01 + T02*Rw02;
    float cc01 = T00*Rw10 + T01*Rw11 + T02*Rw12;
    float cc02 = T00*Rw20 + T01*Rw21 + T02*Rw22;
    float cc11 = T10*Rw10 + T11*Rw11 + T12*Rw12;
    float cc12 = T10*Rw20 + T11*Rw21 + T12*Rw22;
    float cc22 = T20*Rw20 + T21*Rw21 + T22*Rw22;

    float J00 = fx*izs, J02 = -fx*p0*izs*izs;
    float J11 = fy*izs, J12 = -fy*p1*izs*izs;
    float a = J00*(J00*cc00 + J02*cc02) + J02*(J00*cc02 + J02*cc22) + 0.3f;
    float b = J00*(cc01*J11 + cc02*J12) + J02*(cc12*J11 + cc22*J12);
    float c = J11*(J11*cc11 + J12*cc12) + J12*(J11*cc12 + J12*cc22) + 0.3f;

    float det2 = a*c - b*b;
    bool valid = (z > nearf) && (z < farf) && (det2 > 1e-12f);
    float dd  = (det2 > 1e-12f) ? det2 : 1.0f;
    float idd = 1.0f / dd;
    float ia = c*idd, ib = -b*idd, ic = a*idd;

    float op = valid ? opac[n] : 0.0f;
    const float SH_C0 = 0.28209479177387814f;
    float col0 = fmaxf(SH_C0*feat[n*3+0] + 0.5f, 0.0f);
    float col1 = fmaxf(SH_C0*feat[n*3+1] + 0.5f, 0.0f);
    float col2 = fmaxf(SH_C0*feat[n*3+2] + 0.5f, 0.0f);

    // alpha >= 1/255 footprint bbox half-extents (+1 px pad, conservative)
    float rx = -1.0f, ry = -1.0f;
    float tau = 2.0f * logf(255.0f * op);      // = 2*ln(255*op)
    if (valid && op > (1.0f/255.0f) && tau > 0.0f) {
        rx = sqrtf(tau * fmaxf(a, 0.0f)) + 1.0f;
        ry = sqrtf(tau * fmaxf(c, 0.0f)) + 1.0f;
    }

    // pre-folded conic: power = pa*dx^2 + pc*dy^2 + pb*dx*dy
    // pthr: alpha >= 1/255  <=>  power >= -tau/2
    float pthr = (op > (1.0f/255.0f)) ? (-0.5f * tau) : 1.0f;  // 1.0 => never
    d_rawA[n] = make_float4(u, v, -0.5f*ia, -ib);
    d_rawB[n] = make_float4(-0.5f*ic, op, z, pthr);
    d_rawC[n] = make_float4(col0, col1, col2, 0.0f);
    d_zkey[n] = float_to_ordered(z);

    // complement-encoded tile range for __vcmpgeu4 test; miss = 0xFFFFFFFF
    unsigned int tbox = 0xFFFFFFFFu;
    if (rx > 0.0f) {
        int tx0 = (int)ceilf ((u - rx - 7.5f) * 0.125f - 1e-4f);
        int tx1 = (int)floorf((u + rx - 0.5f) * 0.125f + 1e-4f);
        int ty0 = (int)ceilf ((v - ry - 7.5f) * 0.125f - 1e-4f);
        int ty1 = (int)floorf((v + ry - 0.5f) * 0.125f + 1e-4f);
        if (tx0 < 0) tx0 = 0;
        if (ty0 < 0) ty0 = 0;
        if (tx1 > TX - 1) tx1 = TX - 1;
        if (ty1 > TY - 1) ty1 = TY - 1;
        if (tx0 <= tx1 && ty0 <= ty1) {
            tbox = (unsigned int)tx0 |
                   ((unsigned int)(255 - tx1) << 8) |
                   ((unsigned int)ty0 << 16) |
                   ((unsigned int)(255 - ty1) << 24);
        }
    }
    d_tbox[n] = tbox;
    cudaTriggerProgrammaticLaunchCompletion();
}

// ---------------- per-tile (8x8) cull + rank-sort + 8-segment composite -----
__global__ void __launch_bounds__(512)
render_tiles_kernel(int N, int npix, const void* pW, float* __restrict__ out)
{
    __shared__ unsigned long long sh_key[MAXN];            // 16 KB
    __shared__ __align__(16) float4 stA[512];              // 8 KB  [8][64]
    __shared__ __align__(16) float4 stB[512];              // 8 KB
    __shared__ __align__(16) float4 stC[512];              // 8 KB
    __shared__ float segT[512];                            // 2 KB
    __shared__ int s_cnt;

    float4* segC = stA;     // [8][64] aliases stage after composite

    int W = load_scalar_i(pW);
    int H = npix / W;
    int TX = (W + TW - 1) / TW;
    int TY = (H + TW - 1) / TW;
    int nt = TX * TY;
    int t = blockIdx.x;
    if (t >= nt) return;                  // slack block: exit before PDL sync

    int tid = threadIdx.x;
    int lane = tid & 31;
    int txi = t % TX;
    int tyi = t / TX;

    // complement-encoded query for this tile
    unsigned int q = (unsigned int)txi |
                     ((unsigned int)(255 - txi) << 8) |
                     ((unsigned int)tyi << 16) |
                     ((unsigned int)(255 - tyi) << 24);

    if (tid == 0) s_cnt = 0;

    // wait for prep results (PDL)
    cudaGridDependencySynchronize();

    // ---- cull: prefetch 4 tbox chunks, SIMD range test, lazy zkey ----
    unsigned int tbv[4];
    #pragma unroll
    for (int c = 0; c < 4; c++) {
        int g = tid + (c << 9);
        tbv[c] = (g < N) ? d_tbox[g] : 0xFFFFFFFFu;   // miss
    }
    __syncthreads();

    #pragma unroll
    for (int c = 0; c < 4; c++) {
        int g = tid + (c << 9);
        bool hit = (__vcmpgeu4(q, tbv[c]) == 0xFFFFFFFFu);
        unsigned int m = __ballot_sync(0xffffffffu, hit);
        int nb_ = __popc(m);
        int wbase = 0;
        if (lane == 0 && nb_) wbase = atomicAdd(&s_cnt, nb_);
        wbase = __shfl_sync(0xffffffffu, wbase, 0);
        if (hit) {
            int pos = wbase + __popc(m & ((1u << lane) - 1u));
            sh_key[pos] = ((unsigned long long)d_zkey[g] << 32) | (unsigned int)g;
        }
    }
    __syncthreads();
    int cnt = s_cnt;

    // pixel mapping
    int gid = tid >> 6;            // 0..7 (z-segment group)
    int p   = tid & 63;            // pixel within 8x8 tile
    int col = txi * TW + (p % TW);
    int row = tyi * TW + (p / TW);
    bool active = (col < W) && (row < H);

    // ---- empty-tile fast path ----
    if (cnt == 0) {
        if (tid < 64) {
            if (col < W && row < H) {
                int pix = row * W + col;
                out[0*npix + pix] = 0.0f;
                out[1*npix + pix] = 0.0f;
                out[2*npix + pix] = 0.0f;
                out[3*npix + pix] = 0.0f;
            }
        }
        return;
    }

    // ---- barrier-free rank sort (keys unique: idx in low bits) ----
    {
        unsigned long long own[4];
        int rank[4];
        int nown = 0;
        for (int i = tid; i < cnt; i += 512) {
            own[nown] = sh_key[i];
            rank[nown] = 0;
            nown++;
        }
        // single scan over the key list; broadcast LDS reads
        for (int j = 0; j < cnt; j++) {
            unsigned long long kj = sh_key[j];
            #pragma unroll 4
            for (int e = 0; e < 4; e++)
                if (e < nown && kj < own[e]) rank[e]++;
        }
        __syncthreads();   // all scans done before scatter overwrites
        for (int e = 0; e < nown; e++)
            sh_key[rank[e]] = own[e];
        __syncthreads();   // sorted list visible
    }

    // ---- segmented composite: 8 groups of 64 threads, chunk=64 ----
    float px = (float)col + 0.5f;
    float py = (float)row + 0.5f;

    int seg  = (cnt + 7) >> 3;
    int gbeg = gid * seg;
    int gend = min(cnt, gbeg + seg);
    int nchunk = (seg + 63) >> 6;          // uniform across groups

    float T = 1.0f, cr = 0.0f, cg = 0.0f, cb = 0.0f, cd = 0.0f;

    for (int c = 0; c < nchunk; c++) {
        int cbeg = gbeg + (c << 6);
        int m = gend - cbeg;
        if (m > 64) m = 64;
        if (m < 0) m = 0;
        if (p < m) {
            int g = (int)(sh_key[cbeg + p] & 0xFFFFFFFFu);
            stA[(gid << 6) + p] = d_rawA[g];
            stB[(gid << 6) + p] = d_rawB[g];
            stC[(gid << 6) + p] = d_rawC[g];
        }
        __syncthreads();

        if (T > 1e-4f) {
            for (int i = 0; i < m; i++) {
                float4 a4 = stA[(gid << 6) + i];
                float dx = px - a4.x;
                float dy = py - a4.y;
                float4 b4 = stB[(gid << 6) + i];
                float power = fmaf(a4.z, dx*dx,
                              fmaf(b4.x, dy*dy, a4.w*(dx*dy)));
                if (power <= 0.0f && power >= b4.w) {
                    float alpha = fminf(b4.y * __expf(power), 0.99f);
                    if (alpha >= (1.0f/255.0f)) {
                        float w = T * alpha;
                        float4 c4 = stC[(gid << 6) + i];
                        cr += w * c4.x;
                        cg += w * c4.y;
                        cb += w * c4.z;
                        cd += w * b4.z;
                        T *= (1.0f - alpha);
                    }
                }
            }
        }
        __syncthreads();    // stage reused next chunk
    }

    // ---- exact combine across the 8 segments (segC aliases stA) ----
    segC[(gid << 6) + p] = make_float4(cr, cg, cb, cd);
    segT[(gid << 6) + p] = T;
    __syncthreads();

    if (tid < 64 && active) {
        float Tt = 1.0f, r = 0.0f, g2 = 0.0f, b2 = 0.0f, d2 = 0.0f;
        #pragma unroll
        for (int s = 0; s < 8; s++) {
            float4 cs = segC[(s << 6) + tid];
            float  ts = segT[(s << 6) + tid];
            r  += Tt * cs.x;
            g2 += Tt * cs.y;
            b2 += Tt * cs.z;
            d2 += Tt * cs.w;
            Tt *= ts;
        }
        int pix = row * W + col;
        out[0*npix + pix] = r;
        out[1*npix + pix] = g2;
        out[2*npix + pix] = b2;
        out[3*npix + pix] = d2;
    }
}

extern "C" void kernel_launch(void* const* d_in, const int* in_sizes, int n_in,
                              void* d_out, int out_size)
{
    const float* xyz  = (const float*)d_in[0];
    const float* feat = (const float*)d_in[1];
    const float* scal = (const float*)d_in[2];
    const float* rot  = (const float*)d_in[3];
    const float* opac = (const float*)d_in[4];
    const float* c2w  = (const float*)d_in[5];
    const float* intr = (const float*)d_in[6];
    const void*  pW   = d_in[7];
    const void*  pNear = d_in[10];
    const void*  pFar  = d_in[11];

    int N = in_sizes[0] / 3;            // B = 1
    if (N > MAXN) N = MAXN;
    int npix = out_size / 4;            // 4 channels (rgb + depth)

    prep_kernel<<<(N + 255) / 256, 256>>>(xyz, feat, scal, rot, opac,
                                          c2w, intr, pNear, pFar, pW, npix, N);

    int nb = npix / 64 + 80;            // covers all 8x8 tiles incl. ragged

    // PDL: render may launch early; device-side sync gates on prep completion
    cudaLaunchConfig_t cfg = {};
    cfg.gridDim  = dim3((unsigned)nb, 1, 1);
    cfg.blockDim = dim3(512, 1, 1);
    cfg.dynamicSmemBytes = 0;
    cfg.stream = 0;
    cudaLaunchAttribute attrs[1];
    attrs[0].id = cudaLaunchAttributeProgrammaticStreamSerialization;
    attrs[0].val.programmaticStreamSerializationAllowed = 1;
    cfg.attrs = attrs;
    cfg.numAttrs = 1;
    cudaLaunchKernelEx(&cfg, render_tiles_kernel, N, npix, pW, (float*)d_out);
}

// round 15
// speedup vs baseline: 1.6590x; 1.6590x over previous
#include <cuda_runtime.h>
#include <math.h>
#include <float.h>

// ---------------------------------------------------------------------------
// Tiled Gaussian splat renderer (B=1, V=1). Two-kernel graph with PDL overlap:
//  1) prep: per-gaussian projection/conic/color -> SoA + packed 8x8-tile
//     range (complement-encoded u8x4 for SIMD test) + ordered z key.
//  2) render (PDL): one 512-thread block per 8x8 tile:
//       a) cull: prefetch 4 tbox chunks (MLP), __vcmpgeu4 range test,
//          warp-aggregated append of (zkey|idx) into smem
//       b) hybrid bitonic sort on (ordered_z | idx) -> deterministic order
//       c) 8 z-segment groups (64 px each) composite, chunk=64,
//          exact in-smem segment combine.  Empty tiles: zero-fill fast path.
// ---------------------------------------------------------------------------

#define MAXN  2048
#define TW    8

__device__ float4 d_rawA[MAXN], d_rawB[MAXN], d_rawC[MAXN];
__device__ unsigned int d_tbox[MAXN];    // tx0 | (255-tx1)<<8 | ty0<<16 | (255-ty1)<<24
__device__ unsigned int d_zkey[MAXN];    // ordered-float z

// Scalar inputs may arrive as int32 or float32 bit patterns.
__device__ __forceinline__ float load_scalar_f(const void* p) {
    int v = *(const int*)p;
    if (v >= -1000000 && v <= 1000000) return (float)v;
    return __int_as_float(v);
}
__device__ __forceinline__ int load_scalar_i(const void* p) {
    return (int)load_scalar_f(p);
}

__device__ __forceinline__ unsigned int float_to_ordered(float f) {
    unsigned int u = __float_as_uint(f);
    return (u & 0x80000000u) ? ~u : (u | 0x80000000u);
}

// ---------------- per-gaussian preprocess ----------------
__global__ void prep_kernel(const float* __restrict__ xyz,
                            const float* __restrict__ feat,
                            const float* __restrict__ scal,
                            const float* __restrict__ rot,
                            const float* __restrict__ opac,
                            const float* __restrict__ c2w,
                            const float* __restrict__ intr,
                            const void* nearp, const void* farp,
                            const void* pW, int npix, int N)
{
    int n = blockIdx.x * blockDim.x + threadIdx.x;
    if (n >= N) { cudaTriggerProgrammaticLaunchCompletion(); return; }
    float nearf = load_scalar_f(nearp);
    float farf  = load_scalar_f(farp);
    int W = load_scalar_i(pW);
    int H = npix / W;
    int TX = (W + TW - 1) / TW;
    int TY = (H + TW - 1) / TW;

    float4 q4 = *(const float4*)(rot + n*4);
    float qw = q4.x, qx = q4.y, qy = q4.z, qz = q4.w;
    float inr = 1.0f / (sqrtf(qw*qw + qx*qx + qy*qy + qz*qz) + 1e-8f);
    qw *= inr; qx *= inr; qy *= inr; qz *= inr;
    float R00 = 1.0f - 2.0f*(qy*qy + qz*qz);
    float R01 = 2.0f*(qx*qy - qw*qz);
    float R02 = 2.0f*(qx*qz + qw*qy);
    float R10 = 2.0f*(qx*qy + qw*qz);
    float R11 = 1.0f - 2.0f*(qx*qx + qz*qz);
    float R12 = 2.0f*(qy*qz - qw*qx);
    float R20 = 2.0f*(qx*qz - qw*qy);
    float R21 = 2.0f*(qy*qz + qw*qx);
    float R22 = 1.0f - 2.0f*(qx*qx + qy*qy);

    float s0 = scal[n*3+0], s1 = scal[n*3+1], s2 = scal[n*3+2];
    float M00 = R00*s0, M01 = R01*s1, M02 = R02*s2;
    float M10 = R10*s0, M11 = R11*s1, M12 = R12*s2;
    float M20 = R20*s0, M21 = R21*s1, M22 = R22*s2;

    float C00 = M00*M00 + M01*M01 + M02*M02;
    float C01 = M00*M10 + M01*M11 + M02*M12;
    float C02 = M00*M20 + M01*M21 + M02*M22;
    float C11 = M10*M10 + M11*M11 + M12*M12;
    float C12 = M10*M20 + M11*M21 + M12*M22;
    float C22 = M20*M20 + M21*M21 + M22*M22;

    float A00 = c2w[0], A01 = c2w[1], A02 = c2w[2],  tx = c2w[3];
    float A10 = c2w[4], A11 = c2w[5], A12 = c2w[6],  ty = c2w[7];
    float A20 = c2w[8], A21 = c2w[9], A22 = c2w[10], tz = c2w[11];
    float i00 = A11*A22 - A12*A21, i01 = A02*A21 - A01*A22, i02 = A01*A12 - A02*A11;
    float i10 = A12*A20 - A10*A22, i11 = A00*A22 - A02*A20, i12 = A02*A10 - A00*A12;
    float i20 = A10*A21 - A11*A20, i21 = A01*A20 - A00*A21, i22 = A00*A11 - A01*A10;
    float dinv = 1.0f / (A00*i00 + A01*i10 + A02*i20);
    float Rw00 = i00*dinv, Rw01 = i01*dinv, Rw02 = i02*dinv;
    float Rw10 = i10*dinv, Rw11 = i11*dinv, Rw12 = i12*dinv;
    float Rw20 = i20*dinv, Rw21 = i21*dinv, Rw22 = i22*dinv;
    float t0 = -(Rw00*tx + Rw01*ty + Rw02*tz);
    float t1 = -(Rw10*tx + Rw11*ty + Rw12*tz);
    float t2 = -(Rw20*tx + Rw21*ty + Rw22*tz);

    float x0 = xyz[n*3+0], x1 = xyz[n*3+1], x2 = xyz[n*3+2];
    float p0 = Rw00*x0 + Rw01*x1 + Rw02*x2 + t0;
    float p1 = Rw10*x0 + Rw11*x1 + Rw12*x2 + t1;
    float p2 = Rw20*x0 + Rw21*x1 + Rw22*x2 + t2;

    float z  = p2;
    float zs = fmaxf(z, 1e-4f);
    float izs = 1.0f / zs;
    float fx = intr[0], fy = intr[1], cx = intr[2], cy = intr[3];
    float u = fx * p0 * izs + cx;
    float v = fy * p1 * izs + cy;

    float T00 = Rw00*C00 + Rw01*C01 + Rw02*C02;
    float T01 = Rw00*C01 + Rw01*C11 + Rw02*C12;
    float T02 = Rw00*C02 + Rw01*C12 + Rw02*C22;
    float T10 = Rw10*C00 + Rw11*C01 + Rw12*C02;
    float T11 = Rw10*C01 + Rw11*C11 + Rw12*C12;
    float T12 = Rw10*C02 + Rw11*C12 + Rw12*C22;
    float T20 = Rw20*C00 + Rw21*C01 + Rw22*C02;
    float T21 = Rw20*C01 + Rw21*C11 + Rw22*C12;
    float T22 = Rw20*C02 + Rw21*C12 + Rw22*C22;
    float cc00 = T00*Rw00 + T01*Rw01 + T02*Rw02;
    float cc01 = T00*Rw10 + T01*Rw11 + T02*Rw12;
    float cc02 = T00*Rw20 + T01*Rw21 + T02*Rw22;
    float cc11 = T10*Rw10 + T11*Rw11 + T12*Rw12;
    float cc12 = T10*Rw20 + T11*Rw21 + T12*Rw22;
    float cc22 = T20*Rw20 + T21*Rw21 + T22*Rw22;

    float J00 = fx*izs, J02 = -fx*p0*izs*izs;
    float J11 = fy*izs, J12 = -fy*p1*izs*izs;
    float a = J00*(J00*cc00 + J02*cc02) + J02*(J00*cc02 + J02*cc22) + 0.3f;
    float b = J00*(cc01*J11 + cc02*J12) + J02*(cc12*J11 + cc22*J12);
    float c = J11*(J11*cc11 + J12*cc12) + J12*(J11*cc12 + J12*cc22) + 0.3f;

    float det2 = a*c - b*b;
    bool valid = (z > nearf) && (z < farf) && (det2 > 1e-12f);
    float dd  = (det2 > 1e-12f) ? det2 : 1.0f;
    float idd = 1.0f / dd;
    float ia = c*idd, ib = -b*idd, ic = a*idd;

    float op = valid ? opac[n] : 0.0f;
    const float SH_C0 = 0.28209479177387814f;
    float col0 = fmaxf(SH_C0*feat[n*3+0] + 0.5f, 0.0f);
    float col1 = fmaxf(SH_C0*feat[n*3+1] + 0.5f, 0.0f);
    float col2 = fmaxf(SH_C0*feat[n*3+2] + 0.5f, 0.0f);

    // alpha >= 1/255 footprint bbox half-extents (+1 px pad, conservative)
    float rx = -1.0f, ry = -1.0f;
    float tau = 2.0f * logf(255.0f * op);      // = 2*ln(255*op)
    if (valid && op > (1.0f/255.0f) && tau > 0.0f) {
        rx = sqrtf(tau * fmaxf(a, 0.0f)) + 1.0f;
        ry = sqrtf(tau * fmaxf(c, 0.0f)) + 1.0f;
    }

    // pre-folded conic: power = pa*dx^2 + pc*dy^2 + pb*dx*dy
    // pthr: alpha >= 1/255  <=>  power >= -tau/2
    float pthr = (op > (1.0f/255.0f)) ? (-0.5f * tau) : 1.0f;  // 1.0 => never
    d_rawA[n] = make_float4(u, v, -0.5f*ia, -ib);
    d_rawB[n] = make_float4(-0.5f*ic, op, z, pthr);
    d_rawC[n] = make_float4(col0, col1, col2, 0.0f);
    d_zkey[n] = float_to_ordered(z);

    // complement-encoded tile range for __vcmpgeu4 test; miss = 0xFFFFFFFF
    unsigned int tbox = 0xFFFFFFFFu;
    if (rx > 0.0f) {
        int tx0 = (int)ceilf ((u - rx - 7.5f) * 0.125f - 1e-4f);
        int tx1 = (int)floorf((u + rx - 0.5f) * 0.125f + 1e-4f);
        int ty0 = (int)ceilf ((v - ry - 7.5f) * 0.125f - 1e-4f);
        int ty1 = (int)floorf((v + ry - 0.5f) * 0.125f + 1e-4f);
        if (tx0 < 0) tx0 = 0;
        if (ty0 < 0) ty0 = 0;
        if (tx1 > TX - 1) tx1 = TX - 1;
        if (ty1 > TY - 1) ty1 = TY - 1;
        if (tx0 <= tx1 && ty0 <= ty1) {
            tbox = (unsigned int)tx0 |
                   ((unsigned int)(255 - tx1) << 8) |
                   ((unsigned int)ty0 << 16) |
                   ((unsigned int)(255 - ty1) << 24);
        }
    }
    d_tbox[n] = tbox;
    cudaTriggerProgrammaticLaunchCompletion();
}

__device__ __forceinline__ unsigned long long ce_shfl(unsigned long long v,
                                                      int lane, int j, bool up)
{
    unsigned long long p = __shfl_xor_sync(0xffffffffu, v, j);
    bool lower = ((lane & j) == 0);
    unsigned long long mn = min(v, p), mx = max(v, p);
    return (lower == up) ? mn : mx;
}

// ---------------- per-tile (8x8) cull + sort + 8-segment composite ----------
__global__ void __launch_bounds__(512)
render_tiles_kernel(int N, int npix, const void* pW, float* __restrict__ out)
{
    __shared__ unsigned long long sh_key[MAXN];            // 16 KB
    __shared__ __align__(16) float4 stA[512];              // 8 KB  [8][64]
    __shared__ __align__(16) float4 stB[512];              // 8 KB
    __shared__ __align__(16) float4 stC[512];              // 8 KB
    __shared__ float segT[512];                            // 2 KB
    __shared__ int s_cnt;

    float4* segC = stA;     // reuse after composite ([8][64])

    int W = load_scalar_i(pW);
    int H = npix / W;
    int TX = (W + TW - 1) / TW;
    int TY = (H + TW - 1) / TW;
    int nt = TX * TY;
    int t = blockIdx.x;
    if (t >= nt) return;                  // slack block: exit before PDL sync

    int tid = threadIdx.x;
    int lane = tid & 31;
    int txi = t % TX;
    int tyi = t / TX;

    // complement-encoded query for this tile
    unsigned int q = (unsigned int)txi |
                     ((unsigned int)(255 - txi) << 8) |
                     ((unsigned int)tyi << 16) |
                     ((unsigned int)(255 - tyi) << 24);

    if (tid == 0) s_cnt = 0;

    // wait for prep results (PDL)
    cudaGridDependencySynchronize();

    // ---- cull: prefetch all chunks, SIMD range test ----
    unsigned int tbv[4], zkv[4];
    #pragma unroll
    for (int c = 0; c < 4; c++) {
        int g = tid + (c << 9);
        tbv[c] = (g < N) ? d_tbox[g] : 0xFFFFFFFFu;   // miss
    }
    #pragma unroll
    for (int c = 0; c < 4; c++) {
        int g = tid + (c << 9);
        zkv[c] = (g < N) ? d_zkey[g] : 0u;
    }
    __syncthreads();

    #pragma unroll
    for (int c = 0; c < 4; c++) {
        int g = tid + (c << 9);
        bool hit = (__vcmpgeu4(q, tbv[c]) == 0xFFFFFFFFu);
        unsigned int m = __ballot_sync(0xffffffffu, hit);
        int nb_ = __popc(m);
        int wbase = 0;
        if (lane == 0 && nb_) wbase = atomicAdd(&s_cnt, nb_);
        wbase = __shfl_sync(0xffffffffu, wbase, 0);
        if (hit) {
            int pos = wbase + __popc(m & ((1u << lane) - 1u));
            sh_key[pos] = ((unsigned long long)zkv[c] << 32) | (unsigned int)g;
        }
    }
    __syncthreads();
    int cnt = s_cnt;

    // pixel mapping
    int gid = tid >> 6;            // 0..7 (z-segment group)
    int p   = tid & 63;            // pixel within 8x8 tile
    int col = txi * TW + (p % TW);
    int row = tyi * TW + (p / TW);
    bool active = (col < W) && (row < H);

    // ---- empty-tile fast path ----
    if (cnt == 0) {
        if (tid < 64) {
            int c2 = txi * TW + (tid % TW);
            int r2 = tyi * TW + (tid / TW);
            if (c2 < W && r2 < H) {
                int pix = r2 * W + c2;
                out[0*npix + pix] = 0.0f;
                out[1*npix + pix] = 0.0f;
                out[2*npix + pix] = 0.0f;
                out[3*npix + pix] = 0.0f;
            }
        }
        return;
    }

    // ---- hybrid bitonic sort over P = pow2 >= max(64, cnt) ----
    {
        int P = 64;
        while (P < cnt) P <<= 1;
        for (int i = cnt + tid; i < P; i += 512)
            sh_key[i] = 0xFFFFFFFFFFFFFFFFULL;
        __syncthreads();

        int nslots = (P > 512) ? (P >> 9) : 1;

        // k = 2..32: warp-local shuffles
        for (int h = 0; h < nslots; h++) {
            int i = tid + (h << 9);
            if (i < P) {
                unsigned long long v = sh_key[i];
                #pragma unroll
                for (int k = 2; k <= 32; k <<= 1) {
                    bool up = ((i & k) == 0);
                    #pragma unroll
                    for (int j = k >> 1; j > 0; j >>= 1)
                        v = ce_shfl(v, lane, j, up);
                }
                sh_key[i] = v;
            }
        }
        __syncthreads();

        // k = 64..P
        for (int k = 64; k <= P; k <<= 1) {
            for (int j = k >> 1; j >= 32; j >>= 1) {
                for (int h = 0; h < nslots; h++) {
                    int i = tid + (h << 9);
                    int ixj = i ^ j;
                    if (i < P && ixj > i) {
                        bool up = ((i & k) == 0);
                        unsigned long long va = sh_key[i], vb = sh_key[ixj];
                        unsigned long long lo = min(va, vb), hi = max(va, vb);
                        sh_key[i]   = up ? lo : hi;
                        sh_key[ixj] = up ? hi : lo;
                    }
                }
                __syncthreads();
            }
            for (int h = 0; h < nslots; h++) {
                int i = tid + (h << 9);
                if (i < P) {
                    unsigned long long v = sh_key[i];
                    bool up = ((i & k) == 0);
                    #pragma unroll
                    for (int j = 16; j > 0; j >>= 1)
                        v = ce_shfl(v, lane, j, up);
                    sh_key[i] = v;
                }
            }
            __syncthreads();
        }
    }

    // ---- segmented composite: 8 groups of 64 threads, chunk=64 ----
    float px = (float)col + 0.5f;
    float py = (float)row + 0.5f;

    int seg  = (cnt + 7) >> 3;
    int gbeg = gid * seg;
    int gend = min(cnt, gbeg + seg);
    int nchunk = (seg + 63) >> 6;          // uniform across groups

    float T = 1.0f, cr = 0.0f, cg = 0.0f, cb = 0.0f, cd = 0.0f;

    for (int c = 0; c < nchunk; c++) {
        int cbeg = gbeg + (c << 6);
        int m = gend - cbeg;
        if (m > 64) m = 64;
        if (m < 0) m = 0;
        if (p < m) {
            int g = (int)(sh_key[cbeg + p] & 0xFFFFFFFFu);
            stA[(gid << 6) + p] = d_rawA[g];
            stB[(gid << 6) + p] = d_rawB[g];
            stC[(gid << 6) + p] = d_rawC[g];
        }
        __syncthreads();

        if (T > 1e-4f) {
            for (int i = 0; i < m; i++) {
                float4 a4 = stA[(gid << 6) + i];
                float dx = px - a4.x;
                float dy = py - a4.y;
                float4 b4 = stB[(gid << 6) + i];
                float power = fmaf(a4.z, dx*dx,
                              fmaf(b4.x, dy*dy, a4.w*(dx*dy)));
                if (power <= 0.0f && power >= b4.w) {
                    float alpha = fminf(b4.y * __expf(power), 0.99f);
                    if (alpha >= (1.0f/255.0f)) {
                        float w = T * alpha;
                        float4 c4 = stC[(gid << 6) + i];
                        cr += w * c4.x;
                        cg += w * c4.y;
                        cb += w * c4.z;
                        cd += w * b4.z;
                        T *= (1.0f - alpha);
                    }
                }
            }
        }
        __syncthreads();    // stage reused next chunk
    }

    // ---- exact combine across the 8 segments (segC aliases stA) ----
    segC[(gid << 6) + p] = make_float4(cr, cg, cb, cd);
    segT[(gid << 6) + p] = T;
    __syncthreads();

    if (tid < 64 && active) {
        float Tt = 1.0f, r = 0.0f, g2 = 0.0f, b2 = 0.0f, d2 = 0.0f;
        #pragma unroll
        for (int s = 0; s < 8; s++) {
            float4 cs = segC[(s << 6) + tid];
            float  ts = segT[(s << 6) + tid];
            r  += Tt * cs.x;
            g2 += Tt * cs.y;
            b2 += Tt * cs.z;
            d2 += Tt * cs.w;
            Tt *= ts;
        }
        int pix = row * W + col;
        out[0*npix + pix] = r;
        out[1*npix + pix] = g2;
        out[2*npix + pix] = b2;
        out[3*npix + pix] = d2;
    }
}

extern "C" void kernel_launch(void* const* d_in, const int* in_sizes, int n_in,
                              void* d_out, int out_size)
{
    const float* xyz  = (const float*)d_in[0];
    const float* feat = (const float*)d_in[1];
    const float* scal = (const float*)d_in[2];
    const float* rot  = (const float*)d_in[3];
    const float* opac = (const float*)d_in[4];
    const float* c2w  = (const float*)d_in[5];
    const float* intr = (const float*)d_in[6];
    const void*  pW   = d_in[7];
    const void*  pNear = d_in[10];
    const void*  pFar  = d_in[11];

    int N = in_sizes[0] / 3;            // B = 1
    if (N > MAXN) N = MAXN;
    int npix = out_size / 4;            // 4 channels (rgb + depth)

    prep_kernel<<<(N + 255) / 256, 256>>>(xyz, feat, scal, rot, opac,
                                          c2w, intr, pNear, pFar, pW, npix, N);

    int nb = npix / 64 + 80;            // covers all 8x8 tiles incl. ragged

    // PDL: render may launch early; device-side sync gates on prep completion
    cudaLaunchConfig_t cfg = {};
    cfg.gridDim  = dim3((unsigned)nb, 1, 1);
    cfg.blockDim = dim3(512, 1, 1);
    cfg.dynamicSmemBytes = 0;
    cfg.stream = 0;
    cudaLaunchAttribute attrs[1];
    attrs[0].id = cudaLaunchAttributeProgrammaticStreamSerialization;
    attrs[0].val.programmaticStreamSerializationAllowed = 1;
    cfg.attrs = attrs;
    cfg.numAttrs = 1;
    cudaLaunchKernelEx(&cfg, render_tiles_kernel, N, npix, pW, (float*)d_out);
}

// round 16
// speedup vs baseline: 1.8045x; 1.0877x over previous
#include <cuda_runtime.h>
#include <math.h>
#include <float.h>

// ---------------------------------------------------------------------------
// Tiled Gaussian splat renderer (B=1, V=1). Two-kernel graph with PDL overlap:
//  1) prep: per-gaussian projection/conic/color -> SoA + packed 8x8-tile
//     range (complement-encoded u8x4 for SIMD test) + ordered z key.
//     Tight bbox (exact ellipse AABB + 0.3 px guard).
//  2) render (PDL): one 512-thread block per 8x8 tile:
//       a) cull: prefetch 4 tbox chunks, __vcmpgeu4 test, warp-agg append
//       b) hybrid bitonic sort on (ordered_z | idx) -> deterministic order
//       c) 8 z-segment groups (64 px each) composite, chunk=64, 2-load
//          iteration (colors fetched on accept only), exact segment combine.
// ---------------------------------------------------------------------------

#define MAXN  2048
#define TW    8

__device__ float4 d_rawA[MAXN], d_rawB[MAXN], d_rawC[MAXN];
__device__ unsigned int d_tbox[MAXN];    // tx0 | (255-tx1)<<8 | ty0<<16 | (255-ty1)<<24
__device__ unsigned int d_zkey[MAXN];    // ordered-float z

// Scalar inputs may arrive as int32 or float32 bit patterns.
__device__ __forceinline__ float load_scalar_f(const void* p) {
    int v = *(const int*)p;
    if (v >= -1000000 && v <= 1000000) return (float)v;
    return __int_as_float(v);
}
__device__ __forceinline__ int load_scalar_i(const void* p) {
    return (int)load_scalar_f(p);
}

__device__ __forceinline__ unsigned int float_to_ordered(float f) {
    unsigned int u = __float_as_uint(f);
    return (u & 0x80000000u) ? ~u : (u | 0x80000000u);
}

// ---------------- per-gaussian preprocess ----------------
__global__ void prep_kernel(const float* __restrict__ xyz,
                            const float* __restrict__ feat,
                            const float* __restrict__ scal,
                            const float* __restrict__ rot,
                            const float* __restrict__ opac,
                            const float* __restrict__ c2w,
                            const float* __restrict__ intr,
                            const void* nearp, const void* farp,
                            const void* pW, int npix, int N)
{
    int n = blockIdx.x * blockDim.x + threadIdx.x;
    if (n >= N) { cudaTriggerProgrammaticLaunchCompletion(); return; }
    float nearf = load_scalar_f(nearp);
    float farf  = load_scalar_f(farp);
    int W = load_scalar_i(pW);
    int H = npix / W;
    int TX = (W + TW - 1) / TW;
    int TY = (H + TW - 1) / TW;

    float4 q4 = *(const float4*)(rot + n*4);
    float qw = q4.x, qx = q4.y, qy = q4.z, qz = q4.w;
    float inr = 1.0f / (sqrtf(qw*qw + qx*qx + qy*qy + qz*qz) + 1e-8f);
    qw *= inr; qx *= inr; qy *= inr; qz *= inr;
    float R00 = 1.0f - 2.0f*(qy*qy + qz*qz);
    float R01 = 2.0f*(qx*qy - qw*qz);
    float R02 = 2.0f*(qx*qz + qw*qy);
    float R10 = 2.0f*(qx*qy + qw*qz);
    float R11 = 1.0f - 2.0f*(qx*qx + qz*qz);
    float R12 = 2.0f*(qy*qz - qw*qx);
    float R20 = 2.0f*(qx*qz - qw*qy);
    float R21 = 2.0f*(qy*qz + qw*qx);
    float R22 = 1.0f - 2.0f*(qx*qx + qy*qy);

    float s0 = scal[n*3+0], s1 = scal[n*3+1], s2 = scal[n*3+2];
    float M00 = R00*s0, M01 = R01*s1, M02 = R02*s2;
    float M10 = R10*s0, M11 = R11*s1, M12 = R12*s2;
    float M20 = R20*s0, M21 = R21*s1, M22 = R22*s2;

    float C00 = M00*M00 + M01*M01 + M02*M02;
    float C01 = M00*M10 + M01*M11 + M02*M12;
    float C02 = M00*M20 + M01*M21 + M02*M22;
    float C11 = M10*M10 + M11*M11 + M12*M12;
    float C12 = M10*M20 + M11*M21 + M12*M22;
    float C22 = M20*M20 + M21*M21 + M22*M22;

    float A00 = c2w[0], A01 = c2w[1], A02 = c2w[2],  tx = c2w[3];
    float A10 = c2w[4], A11 = c2w[5], A12 = c2w[6],  ty = c2w[7];
    float A20 = c2w[8], A21 = c2w[9], A22 = c2w[10], tz = c2w[11];
    float i00 = A11*A22 - A12*A21, i01 = A02*A21 - A01*A22, i02 = A01*A12 - A02*A11;
    float i10 = A12*A20 - A10*A22, i11 = A00*A22 - A02*A20, i12 = A02*A10 - A00*A12;
    float i20 = A10*A21 - A11*A20, i21 = A01*A20 - A00*A21, i22 = A00*A11 - A01*A10;
    float dinv = 1.0f / (A00*i00 + A01*i10 + A02*i20);
    float Rw00 = i00*dinv, Rw01 = i01*dinv, Rw02 = i02*dinv;
    float Rw10 = i10*dinv, Rw11 = i11*dinv, Rw12 = i12*dinv;
    float Rw20 = i20*dinv, Rw21 = i21*dinv, Rw22 = i22*dinv;
    float t0 = -(Rw00*tx + Rw01*ty + Rw02*tz);
    float t1 = -(Rw10*tx + Rw11*ty + Rw12*tz);
    float t2 = -(Rw20*tx + Rw21*ty + Rw22*tz);

    float x0 = xyz[n*3+0], x1 = xyz[n*3+1], x2 = xyz[n*3+2];
    float p0 = Rw00*x0 + Rw01*x1 + Rw02*x2 + t0;
    float p1 = Rw10*x0 + Rw11*x1 + Rw12*x2 + t1;
    float p2 = Rw20*x0 + Rw21*x1 + Rw22*x2 + t2;

    float z  = p2;
    float zs = fmaxf(z, 1e-4f);
    float izs = 1.0f / zs;
    float fx = intr[0], fy = intr[1], cx = intr[2], cy = intr[3];
    float u = fx * p0 * izs + cx;
    float v = fy * p1 * izs + cy;

    float T00 = Rw00*C00 + Rw01*C01 + Rw02*C02;
    float T01 = Rw00*C01 + Rw01*C11 + Rw02*C12;
    float T02 = Rw00*C02 + Rw01*C12 + Rw02*C22;
    float T10 = Rw10*C00 + Rw11*C01 + Rw12*C02;
    float T11 = Rw10*C01 + Rw11*C11 + Rw12*C12;
    float T12 = Rw10*C02 + Rw11*C12 + Rw12*C22;
    float T20 = Rw20*C00 + Rw21*C01 + Rw22*C02;
    float T21 = Rw20*C01 + Rw21*C11 + Rw22*C12;
    float T22 = Rw20*C02 + Rw21*C12 + Rw22*C22;
    float cc00 = T00*Rw00 + T01*Rw01 + T02*Rw02;
    float cc01 = T00*Rw10 + T01*Rw11 + T02*Rw12;
    float cc02 = T00*Rw20 + T01*Rw21 + T02*Rw22;
    float cc11 = T10*Rw10 + T11*Rw11 + T12*Rw12;
    float cc12 = T10*Rw20 + T11*Rw21 + T12*Rw22;
    float cc22 = T20*Rw20 + T21*Rw21 + T22*Rw22;

    float J00 = fx*izs, J02 = -fx*p0*izs*izs;
    float J11 = fy*izs, J12 = -fy*p1*izs*izs;
    float a = J00*(J00*cc00 + J02*cc02) + J02*(J00*cc02 + J02*cc22) + 0.3f;
    float b = J00*(cc01*J11 + cc02*J12) + J02*(cc12*J11 + cc22*J12);
    float c = J11*(J11*cc11 + J12*cc12) + J12*(J11*cc12 + J12*cc22) + 0.3f;

    float det2 = a*c - b*b;
    bool valid = (z > nearf) && (z < farf) && (det2 > 1e-12f);
    float dd  = (det2 > 1e-12f) ? det2 : 1.0f;
    float idd = 1.0f / dd;
    float ia = c*idd, ib = -b*idd, ic = a*idd;

    float op = valid ? opac[n] : 0.0f;
    const float SH_C0 = 0.28209479177387814f;
    float col0 = fmaxf(SH_C0*feat[n*3+0] + 0.5f, 0.0f);
    float col1 = fmaxf(SH_C0*feat[n*3+1] + 0.5f, 0.0f);
    float col2 = fmaxf(SH_C0*feat[n*3+2] + 0.5f, 0.0f);

    // alpha >= 1/255 footprint: exact ellipse AABB + 0.3 px guard
    float rx = -1.0f, ry = -1.0f;
    float tau = 2.0f * logf(255.0f * op);      // = 2*ln(255*op)
    if (valid && op > (1.0f/255.0f) && tau > 0.0f) {
        rx = sqrtf(tau * fmaxf(a, 0.0f)) + 0.3f;
        ry = sqrtf(tau * fmaxf(c, 0.0f)) + 0.3f;
    }

    // pre-folded conic: power = pa*dx^2 + pc*dy^2 + pb*dx*dy
    // pthr: alpha >= 1/255  <=>  power >= -tau/2
    float pthr = (op > (1.0f/255.0f)) ? (-0.5f * tau) : 1.0f;  // 1.0 => never
    d_rawA[n] = make_float4(u, v, -0.5f*ia, -ib);
    d_rawB[n] = make_float4(-0.5f*ic, pthr, op, z);
    d_rawC[n] = make_float4(col0, col1, col2, 0.0f);
    d_zkey[n] = float_to_ordered(z);

    // complement-encoded tile range for __vcmpgeu4 test; miss = 0xFFFFFFFF
    unsigned int tbox = 0xFFFFFFFFu;
    if (rx > 0.0f) {
        int tx0 = (int)ceilf ((u - rx - 7.5f) * 0.125f - 1e-4f);
        int tx1 = (int)floorf((u + rx - 0.5f) * 0.125f + 1e-4f);
        int ty0 = (int)ceilf ((v - ry - 7.5f) * 0.125f - 1e-4f);
        int ty1 = (int)floorf((v + ry - 0.5f) * 0.125f + 1e-4f);
        if (tx0 < 0) tx0 = 0;
        if (ty0 < 0) ty0 = 0;
        if (tx1 > TX - 1) tx1 = TX - 1;
        if (ty1 > TY - 1) ty1 = TY - 1;
        if (tx0 <= tx1 && ty0 <= ty1) {
            tbox = (unsigned int)tx0 |
                   ((unsigned int)(255 - tx1) << 8) |
                   ((unsigned int)ty0 << 16) |
                   ((unsigned int)(255 - ty1) << 24);
        }
    }
    d_tbox[n] = tbox;
    cudaTriggerProgrammaticLaunchCompletion();
}

__device__ __forceinline__ unsigned long long ce_shfl(unsigned long long v,
                                                      int lane, int j, bool up)
{
    unsigned long long p = __shfl_xor_sync(0xffffffffu, v, j);
    bool lower = ((lane & j) == 0);
    unsigned long long mn = min(v, p), mx = max(v, p);
    return (lower == up) ? mn : mx;
}

// ---------------- per-tile (8x8) cull + sort + 8-segment composite ----------
__global__ void __launch_bounds__(512)
render_tiles_kernel(int N, int npix, const void* pW, float* __restrict__ out)
{
    __shared__ unsigned long long sh_key[MAXN];            // 16 KB
    __shared__ __align__(16) float4 stA[512];              // 8 KB  [8][64]
    __shared__ __align__(16) float4 stB[512];              // 8 KB
    __shared__ __align__(16) float4 stC[512];              // 8 KB
    __shared__ float segT[512];                            // 2 KB
    __shared__ int s_cnt;

    float4* segC = stA;     // reuse after composite ([8][64])

    int W = load_scalar_i(pW);
    int H = npix / W;
    int TX = (W + TW - 1) / TW;
    int TY = (H + TW - 1) / TW;
    int nt = TX * TY;
    int t = blockIdx.x;
    if (t >= nt) return;                  // slack block: exit before PDL sync

    int tid = threadIdx.x;
    int lane = tid & 31;
    int txi = t % TX;
    int tyi = t / TX;

    // complement-encoded query for this tile
    unsigned int q = (unsigned int)txi |
                     ((unsigned int)(255 - txi) << 8) |
                     ((unsigned int)tyi << 16) |
                     ((unsigned int)(255 - tyi) << 24);

    if (tid == 0) s_cnt = 0;

    // wait for prep results (PDL)
    cudaGridDependencySynchronize();

    // ---- cull: prefetch all chunks, SIMD range test ----
    unsigned int tbv[4], zkv[4];
    #pragma unroll
    for (int c = 0; c < 4; c++) {
        int g = tid + (c << 9);
        tbv[c] = (g < N) ? d_tbox[g] : 0xFFFFFFFFu;   // miss
    }
    #pragma unroll
    for (int c = 0; c < 4; c++) {
        int g = tid + (c << 9);
        zkv[c] = (g < N) ? d_zkey[g] : 0u;
    }
    __syncthreads();

    #pragma unroll
    for (int c = 0; c < 4; c++) {
        int g = tid + (c << 9);
        bool hit = (__vcmpgeu4(q, tbv[c]) == 0xFFFFFFFFu);
        unsigned int m = __ballot_sync(0xffffffffu, hit);
        int nb_ = __popc(m);
        int wbase = 0;
        if (lane == 0 && nb_) wbase = atomicAdd(&s_cnt, nb_);
        wbase = __shfl_sync(0xffffffffu, wbase, 0);
        if (hit) {
            int pos = wbase + __popc(m & ((1u << lane) - 1u));
            sh_key[pos] = ((unsigned long long)zkv[c] << 32) | (unsigned int)g;
        }
    }
    __syncthreads();
    int cnt = s_cnt;

    // pixel mapping
    int gid = tid >> 6;            // 0..7 (z-segment group)
    int p   = tid & 63;            // pixel within 8x8 tile
    int col = txi * TW + (p % TW);
    int row = tyi * TW + (p / TW);
    bool active = (col < W) && (row < H);

    // ---- empty-tile fast path ----
    if (cnt == 0) {
        if (tid < 64) {
            int c2 = txi * TW + (tid % TW);
            int r2 = tyi * TW + (tid / TW);
            if (c2 < W && r2 < H) {
                int pix = r2 * W + c2;
                out[0*npix + pix] = 0.0f;
                out[1*npix + pix] = 0.0f;
                out[2*npix + pix] = 0.0f;
                out[3*npix + pix] = 0.0f;
            }
        }
        return;
    }

    // ---- hybrid bitonic sort over P = pow2 >= max(64, cnt) ----
    {
        int P = 64;
        while (P < cnt) P <<= 1;
        for (int i = cnt + tid; i < P; i += 512)
            sh_key[i] = 0xFFFFFFFFFFFFFFFFULL;
        __syncthreads();

        int nslots = (P > 512) ? (P >> 9) : 1;

        // k = 2..32: warp-local shuffles
        for (int h = 0; h < nslots; h++) {
            int i = tid + (h << 9);
            if (i < P) {
                unsigned long long v = sh_key[i];
                #pragma unroll
                for (int k = 2; k <= 32; k <<= 1) {
                    bool up = ((i & k) == 0);
                    #pragma unroll
                    for (int j = k >> 1; j > 0; j >>= 1)
                        v = ce_shfl(v, lane, j, up);
                }
                sh_key[i] = v;
            }
        }
        __syncthreads();

        // k = 64..P
        for (int k = 64; k <= P; k <<= 1) {
            for (int j = k >> 1; j >= 32; j >>= 1) {
                for (int h = 0; h < nslots; h++) {
                    int i = tid + (h << 9);
                    int ixj = i ^ j;
                    if (i < P && ixj > i) {
                        bool up = ((i & k) == 0);
                        unsigned long long va = sh_key[i], vb = sh_key[ixj];
                        unsigned long long lo = min(va, vb), hi = max(va, vb);
                        sh_key[i]   = up ? lo : hi;
                        sh_key[ixj] = up ? hi : lo;
                    }
                }
                __syncthreads();
            }
            for (int h = 0; h < nslots; h++) {
                int i = tid + (h << 9);
                if (i < P) {
                    unsigned long long v = sh_key[i];
                    bool up = ((i & k) == 0);
                    #pragma unroll
                    for (int j = 16; j > 0; j >>= 1)
                        v = ce_shfl(v, lane, j, up);
                    sh_key[i] = v;
                }
            }
            __syncthreads();
        }
    }

    // ---- segmented composite: 8 groups of 64 threads, chunk=64 ----
    float px = (float)col + 0.5f;
    float py = (float)row + 0.5f;

    int seg  = (cnt + 7) >> 3;
    int gbeg = gid * seg;
    int gend = min(cnt, gbeg + seg);
    int nchunk = (seg + 63) >> 6;          // uniform across groups

    float T = 1.0f, cr = 0.0f, cg = 0.0f, cb = 0.0f, cd = 0.0f;

    for (int c = 0; c < nchunk; c++) {
        int cbeg = gbeg + (c << 6);
        int m = gend - cbeg;
        if (m > 64) m = 64;
        if (m < 0) m = 0;
        if (p < m) {
            int g = (int)(sh_key[cbeg + p] & 0xFFFFFFFFu);
            stA[(gid << 6) + p] = d_rawA[g];
            stB[(gid << 6) + p] = d_rawB[g];
            stC[(gid << 6) + p] = d_rawC[g];
        }
        __syncthreads();

        if (T > 1e-4f) {
            const float4* bA = stA + (gid << 6);
            const float4* bB = stB + (gid << 6);
            const float4* bC = stC + (gid << 6);
            #pragma unroll 2
            for (int i = 0; i < m; i++) {
                float4 a4 = bA[i];
                float dx = px - a4.x;
                float dy = py - a4.y;
                float4 b4 = bB[i];           // pc, pthr, op, z
                float power = fmaf(a4.z, dx*dx,
                              fmaf(b4.x, dy*dy, a4.w*(dx*dy)));
                if (power <= 0.0f && power >= b4.y) {
                    float alpha = fminf(b4.z * __expf(power), 0.99f);
                    if (alpha >= (1.0f/255.0f)) {
                        float w = T * alpha;
                        float4 c4 = bC[i];   // loaded only on accept
                        cr += w * c4.x;
                        cg += w * c4.y;
                        cb += w * c4.z;
                        cd += w * b4.w;
                        T *= (1.0f - alpha);
                    }
                }
            }
        }
        __syncthreads();    // stage reused next chunk
    }

    // ---- exact combine across the 8 segments (segC aliases stA) ----
    segC[(gid << 6) + p] = make_float4(cr, cg, cb, cd);
    segT[(gid << 6) + p] = T;
    __syncthreads();

    if (tid < 64 && active) {
        float Tt = 1.0f, r = 0.0f, g2 = 0.0f, b2 = 0.0f, d2 = 0.0f;
        #pragma unroll
        for (int s = 0; s < 8; s++) {
            float4 cs = segC[(s << 6) + tid];
            float  ts = segT[(s << 6) + tid];
            r  += Tt * cs.x;
            g2 += Tt * cs.y;
            b2 += Tt * cs.z;
            d2 += Tt * cs.w;
            Tt *= ts;
        }
        int pix = row * W + col;
        out[0*npix + pix] = r;
        out[1*npix + pix] = g2;
        out[2*npix + pix] = b2;
        out[3*npix + pix] = d2;
    }
}

extern "C" void kernel_launch(void* const* d_in, const int* in_sizes, int n_in,
                              void* d_out, int out_size)
{
    const float* xyz  = (const float*)d_in[0];
    const float* feat = (const float*)d_in[1];
    const float* scal = (const float*)d_in[2];
    const float* rot  = (const float*)d_in[3];
    const float* opac = (const float*)d_in[4];
    const float* c2w  = (const float*)d_in[5];
    const float* intr = (const float*)d_in[6];
    const void*  pW   = d_in[7];
    const void*  pNear = d_in[10];
    const void*  pFar  = d_in[11];

    int N = in_sizes[0] / 3;            // B = 1
    if (N > MAXN) N = MAXN;
    int npix = out_size / 4;            // 4 channels (rgb + depth)

    prep_kernel<<<(N + 255) / 256, 256>>>(xyz, feat, scal, rot, opac,
                                          c2w, intr, pNear, pFar, pW, npix, N);

    int nb = npix / 64 + 80;            // covers all 8x8 tiles incl. ragged

    // PDL: render may launch early; device-side sync gates on prep completion
    cudaLaunchConfig_t cfg = {};
    cfg.gridDim  = dim3((unsigned)nb, 1, 1);
    cfg.blockDim = dim3(512, 1, 1);
    cfg.dynamicSmemBytes = 0;
    cfg.stream = 0;
    cudaLaunchAttribute attrs[1];
    attrs[0].id = cudaLaunchAttributeProgrammaticStreamSerialization;
    attrs[0].val.programmaticStreamSerializationAllowed = 1;
    cfg.attrs = attrs;
    cfg.numAttrs = 1;
    cudaLaunchKernelEx(&cfg, render_tiles_kernel, N, npix, pW, (float*)d_out);
}